// round 9
// baseline (speedup 1.0000x reference)
#include <cuda_runtime.h>
#include <math.h>
#include <stdint.h>

#define LEV 60
#define BATCH 4096
#define NXI 4
#define NH 64
#define NMEM 64
#define NSFC 17
#define NYO 4
#define NG 256
#define NWCOL 320
#define TB 32
#define NBLOCKS 128
#define XC 320
#define KP 72            // padded K for tensor tiles
#define WST 168          // W smem stride in xpre (conflict-free B frags)
#define KD2 68           // padded K (=64) stride in seq kernels
#define LPB 4

#define OFF_SFC (BATCH * LEV * NYO)
#define OFF_MEM (OFF_SFC + BATCH * 3)

__device__ float g_scratch[(size_t)LEV * BATCH * NH];
__device__ float g_X1[(size_t)LEV * BATCH * XC];
__device__ float g_X2[(size_t)LEV * BATCH * XC];

struct Params {
    const float *inputs_main, *inputs_aux, *rnn1_mem, *eps1, *eps2, *eps_sfc;
    const float *W_sfc, *b_sfc, *W_sfc2, *b_sfc2, *W_toa, *b_toa, *W_toa2, *b_toa2;
    const float *Wx1, *Wh1, *Wxs1, *Whs1, *Wx2, *Wh2, *Wxs2, *Whs2;
    const float *W_lat, *b_lat, *W_out, *b_out, *W_sfcout, *b_sfcout;
    const float *W_mu, *b_mu, *W_lv, *b_lv;
    float *out;
};

__device__ __forceinline__ float sigmoidf_(float x) {
    return __fdividef(1.0f, 1.0f + __expf(-x));
}
__device__ __forceinline__ float tanhf_(float x) {
    float ax = fabsf(x);
    float e  = __expf(2.0f * ax);
    float t  = 1.0f - __fdividef(2.0f, e + 1.0f);
    return copysignf(t, x);
}
__device__ __forceinline__ unsigned long long fma2_(unsigned long long a,
                                                    unsigned long long b,
                                                    unsigned long long c) {
    unsigned long long d;
    asm("fma.rn.f32x2 %0, %1, %2, %3;" : "=l"(d) : "l"(a), "l"(b), "l"(c));
    return d;
}
__device__ __forceinline__ float pairsum_(unsigned long long v) {
    float lo = __int_as_float((int)(v & 0xffffffffull));
    float hi = __int_as_float((int)(v >> 32));
    return lo + hi;
}
__device__ __forceinline__ uint32_t tf32_(float x) {
    uint32_t r;
    asm("cvt.rna.tf32.f32 %0, %1;" : "=r"(r) : "f"(x));
    return r;
}
#define MMA_TF32(C, A, B0, B1)                                                  \
    asm volatile("mma.sync.aligned.m16n8k8.row.col.f32.tf32.tf32.f32 "          \
        "{%0,%1,%2,%3},{%4,%5,%6,%7},{%8,%9},{%0,%1,%2,%3};"                    \
        : "+f"((C)[0]), "+f"((C)[1]), "+f"((C)[2]), "+f"((C)[3])                \
        : "r"((A)[0]), "r"((A)[1]), "r"((A)[2]), "r"((A)[3]), "r"(B0), "r"(B1))

// =====================================================================
// xpre: X = A @ [Wa|Wb] via tf32-split mma.sync.
// mode 0: A = [inputs_main|rnn1_mem] at level 59-s (K=68) -> g_X1
// mode 1: A = g_scratch[s] (K=64)                        -> g_X2
// grid: 60 s * 32 btiles * 2 n-halves = 3840 blocks, 256 thr (8 warps)
// block tile: M=128, N=160. warp: 16 rows x 160 cols.
// =====================================================================
#define XPRE_FLOATS (128 * KP + 2 * KP * WST)
#define XPRE_SMEM (XPRE_FLOATS * 4)

extern __shared__ float smem[];

__global__ __launch_bounds__(256, 1)
void xpre_kernel(int mode, const float* __restrict__ im,
                 const float* __restrict__ mem,
                 const float* __restrict__ Wa, const float* __restrict__ Wb) {
    float* A_s = smem;                 // [128][KP]
    float* Whi = smem + 128 * KP;      // [KP][WST]
    float* Wlo = Whi + KP * WST;
    const int tid = threadIdx.x;
    const int bid = blockIdx.x;
    const int s = bid >> 6;
    const int bt = (bid >> 1) & 31;
    const int nbase = (bid & 1) * 160;
    const int K = mode ? 64 : 68;
    float* Xout = mode ? g_X2 : g_X1;

    for (int idx = tid; idx < 128 * KP; idx += 256) {
        int r = idx / KP, k = idx % KP;
        float v = 0.f;
        if (mode == 0) {
            if (k < 68) {
                int b = bt * 128 + r, l = LEV - 1 - s;
                v = (k < NXI) ? im[((size_t)b * LEV + l) * NXI + k]
                              : mem[((size_t)b * LEV + l) * NMEM + (k - NXI)];
            }
        } else if (k < NH) {
            v = g_scratch[((size_t)s * BATCH + bt * 128 + r) * NH + k];
        }
        A_s[r * KP + k] = v;
    }
    for (int idx = tid; idx < KP * 160; idx += 256) {
        int k = idx / 160, jj = idx % 160;
        float v = 0.f;
        if (k < K) {
            int j = nbase + jj;
            v = (j < NG) ? Wa[(size_t)k * NG + j] : Wb[(size_t)k * NH + (j - NG)];
        }
        float hf = __uint_as_float(__float_as_uint(v) & 0xFFFFE000u);
        Whi[k * WST + jj] = hf;
        Wlo[k * WST + jj] = __uint_as_float(tf32_(v - hf));
    }
    __syncthreads();

    const int w = tid >> 5, lane = tid & 31;
    const int gq = lane >> 2, tq = lane & 3;
    float c[20][4];
#pragma unroll
    for (int n = 0; n < 20; n++) { c[n][0] = c[n][1] = c[n][2] = c[n][3] = 0.f; }

    for (int k0 = 0; k0 < KP; k0 += 8) {
        uint32_t ahi[4], alo[4];
#pragma unroll
        for (int i = 0; i < 4; i++) {
            int rr = w * 16 + gq + (i & 1) * 8;
            int kk = k0 + tq + (i >> 1) * 4;
            float a = A_s[rr * KP + kk];
            ahi[i] = __float_as_uint(a) & 0xFFFFE000u;
            alo[i] = tf32_(a - __uint_as_float(ahi[i]));
        }
#pragma unroll
        for (int n0 = 0; n0 < 20; n0++) {
            int jj = n0 * 8 + gq;
            uint32_t bh0 = __float_as_uint(Whi[(k0 + tq) * WST + jj]);
            uint32_t bh1 = __float_as_uint(Whi[(k0 + tq + 4) * WST + jj]);
            uint32_t bl0 = __float_as_uint(Wlo[(k0 + tq) * WST + jj]);
            uint32_t bl1 = __float_as_uint(Wlo[(k0 + tq + 4) * WST + jj]);
            MMA_TF32(c[n0], ahi, bh0, bh1);
            MMA_TF32(c[n0], ahi, bl0, bl1);
            MMA_TF32(c[n0], alo, bh0, bh1);
        }
    }
    size_t rb = (size_t)s * BATCH + bt * 128;
#pragma unroll
    for (int n0 = 0; n0 < 20; n0++) {
        int col = nbase + n0 * 8 + tq * 2;
        int r0 = w * 16 + gq;
        *(float2*)&Xout[(rb + r0) * XC + col]       = make_float2(c[n0][0], c[n0][1]);
        *(float2*)&Xout[(rb + r0 + 8) * XC + col]   = make_float2(c[n0][2], c[n0][3]);
    }
}

// =====================================================================
// Sequential h-only recurrence, K=64 (R3 structure, gacc in smem)
// =====================================================================
#define SM2_W    (NWCOL * KD2)
#define SM2_XH   (TB * KD2)
#define SM2_GACC (TB * NWCOL)
#define SEQ_SMEM ((SM2_W + SM2_XH + SM2_GACC) * 4)

__device__ __forceinline__ void gemm64_(const float* __restrict__ W_s,
                                        const float* __restrict__ xh,
                                        float* __restrict__ gacc,
                                        int tx, int ty) {
    unsigned long long acc[8][5];
#pragma unroll
    for (int u = 0; u < 8; u++)
#pragma unroll
        for (int c = 0; c < 5; c++) acc[u][c] = 0ull;
#pragma unroll 1
    for (int kq = 0; kq < 16; kq++) {
        ulonglong2 wv[5];
#pragma unroll
        for (int c = 0; c < 5; c++)
            wv[c] = *(const ulonglong2*)&W_s[(c * 64 + tx) * KD2 + kq * 4];
#pragma unroll
        for (int u = 0; u < 8; u++) {
            ulonglong2 xv = *(const ulonglong2*)&xh[(ty * 8 + u) * KD2 + kq * 4];
#pragma unroll
            for (int c = 0; c < 5; c++) {
                acc[u][c] = fma2_(xv.x, wv[c].x, acc[u][c]);
                acc[u][c] = fma2_(xv.y, wv[c].y, acc[u][c]);
            }
        }
    }
#pragma unroll
    for (int u = 0; u < 8; u++)
#pragma unroll
        for (int c = 0; c < 5; c++)
            gacc[(ty * 8 + u) * NWCOL + c * 64 + tx] = pairsum_(acc[u][c]);
}

__device__ __forceinline__ void pointwise64_(float* __restrict__ xh,
                                             const float* __restrict__ gacc,
                                             float* __restrict__ c_reg,
                                             int pr, int pj0,
                                             const float* __restrict__ Xr,
                                             const float* __restrict__ eps_ptr,
                                             float* __restrict__ hout_ptr) {
    float ge[8];
    *(float4*)&ge[0] = *(const float4*)(eps_ptr);
    *(float4*)&ge[4] = *(const float4*)(eps_ptr + 4);
    const float* g = gacc + pr * NWCOL + pj0;
    float gi[8], gf[8], gg[8], go[8], gv[8];
    *(float4*)&gi[0] = *(const float4*)(g);        *(float4*)&gi[4] = *(const float4*)(g + 4);
    *(float4*)&gf[0] = *(const float4*)(g + 64);   *(float4*)&gf[4] = *(const float4*)(g + 68);
    *(float4*)&gg[0] = *(const float4*)(g + 128);  *(float4*)&gg[4] = *(const float4*)(g + 132);
    *(float4*)&go[0] = *(const float4*)(g + 192);  *(float4*)&go[4] = *(const float4*)(g + 196);
    *(float4*)&gv[0] = *(const float4*)(g + 256);  *(float4*)&gv[4] = *(const float4*)(g + 260);
    float hs[8];
#pragma unroll
    for (int u = 0; u < 8; u++) {
        float iv = sigmoidf_(gi[u] + Xr[u]);
        float fv = sigmoidf_(gf[u] + Xr[8 + u]);
        float gt = tanhf_(gg[u] + Xr[16 + u]);
        float ov = sigmoidf_(go[u] + Xr[24 + u]);
        float cc = fv * c_reg[u] + iv * gt;
        c_reg[u] = cc;
        float h  = ov * tanhf_(cc) + ge[u] * __expf(0.5f * (gv[u] + Xr[32 + u]));
        xh[pr * KD2 + pj0 + u] = h;
        hs[u] = h;
    }
    *(float4*)(hout_ptr)     = *(const float4*)&hs[0];
    *(float4*)(hout_ptr + 4) = *(const float4*)&hs[4];
}

__global__ __launch_bounds__(256, 1)
void rnn1_seq(Params p) {
    const int tid = threadIdx.x;
    const int b0  = blockIdx.x * TB;
    float* W_s  = smem;
    float* xh   = smem + SM2_W;
    float* gacc = xh + SM2_XH;
    const int pr = tid >> 3, pj0 = (tid & 7) * 8;
    const int tx = tid & 63, ty = tid >> 6;
    float c_reg[8];

    for (int idx = tid; idx < NWCOL * KD2; idx += 256) {
        int j = idx / KD2, k = idx % KD2;
        float v = 0.f;
        if (k < NH) v = (j < NG) ? p.Wh1[(size_t)k * NG + j]
                                 : p.Whs1[(size_t)k * NH + (j - NG)];
        W_s[idx] = v;
    }
    {   // h0/c0 from surface MLPs; zero pad cols
        const float* auxrow = p.inputs_aux + (size_t)(b0 + pr) * NSFC;
#pragma unroll
        for (int u = 0; u < 8; u++) {
            int j = pj0 + u;
            float ah = p.b_sfc[j], ac = p.b_sfc2[j];
            for (int k = 0; k < NSFC; k++) {
                float a = auxrow[k];
                ah = fmaf(a, p.W_sfc[k * NH + j], ah);
                ac = fmaf(a, p.W_sfc2[k * NH + j], ac);
            }
            xh[pr * KD2 + j] = tanhf_(ah);
            c_reg[u] = tanhf_(ac);
        }
        if (tid < TB * 4) xh[(tid >> 2) * KD2 + NH + (tid & 3)] = 0.f;
    }
    __syncthreads();

    for (int s = 0; s < LEV; s++) {
        int l = LEV - 1 - s;
        float Xr[40];
        {
            const float* xp = g_X1 + ((size_t)s * BATCH + b0 + pr) * XC + pj0;
#pragma unroll
            for (int c = 0; c < 5; c++) {
                *(float4*)&Xr[c * 8 + 0] = *(const float4*)(xp + c * 64);
                *(float4*)&Xr[c * 8 + 4] = *(const float4*)(xp + c * 64 + 4);
            }
        }
        gemm64_(W_s, xh, gacc, tx, ty);
        __syncthreads();
        pointwise64_(xh, gacc, c_reg, pr, pj0, Xr,
                     p.eps1 + ((size_t)s * BATCH + b0 + pr) * NH + pj0,
                     g_scratch + ((size_t)l * BATCH + b0 + pr) * NH + pj0);
        __syncthreads();
    }
}

__global__ __launch_bounds__(256, 1)
void rnn2_seq(Params p) {
    const int tid = threadIdx.x;
    const int b0  = blockIdx.x * TB;
    float* W_s  = smem;
    float* xh   = smem + SM2_W;
    float* gacc = xh + SM2_XH;
    const int pr = tid >> 3, pj0 = (tid & 7) * 8;
    const int tx = tid & 63, ty = tid >> 6;
    float c_reg[8];

    for (int idx = tid; idx < NWCOL * KD2; idx += 256) {
        int j = idx / KD2, k = idx % KD2;
        float v = 0.f;
        if (k < NH) v = (j < NG) ? p.Wh2[(size_t)k * NG + j]
                                 : p.Whs2[(size_t)k * NH + (j - NG)];
        W_s[idx] = v;
    }
    {   // h0/c0 from TOA MLPs (aux cols 1 and 6)
        float x0 = p.inputs_aux[(size_t)(b0 + pr) * NSFC + 1];
        float x1 = p.inputs_aux[(size_t)(b0 + pr) * NSFC + 6];
#pragma unroll
        for (int u = 0; u < 8; u++) {
            int j = pj0 + u;
            float ah = fmaf(x0, p.W_toa[j],  fmaf(x1, p.W_toa[NH + j],  p.b_toa[j]));
            float ac = fmaf(x0, p.W_toa2[j], fmaf(x1, p.W_toa2[NH + j], p.b_toa2[j]));
            xh[pr * KD2 + j] = tanhf_(ah);
            c_reg[u] = tanhf_(ac);
        }
        if (tid < TB * 4) xh[(tid >> 2) * KD2 + NH + (tid & 3)] = 0.f;
    }
    __syncthreads();

    for (int s = 0; s < LEV; s++) {
        float Xr[40];
        {
            const float* xp = g_X2 + ((size_t)s * BATCH + b0 + pr) * XC + pj0;
#pragma unroll
            for (int c = 0; c < 5; c++) {
                *(float4*)&Xr[c * 8 + 0] = *(const float4*)(xp + c * 64);
                *(float4*)&Xr[c * 8 + 4] = *(const float4*)(xp + c * 64 + 4);
            }
        }
        gemm64_(W_s, xh, gacc, tx, ty);
        __syncthreads();
        pointwise64_(xh, gacc, c_reg, pr, pj0, Xr,
                     p.eps2 + ((size_t)s * BATCH + b0 + pr) * NH + pj0,
                     g_scratch + ((size_t)s * BATCH + b0 + pr) * NH + pj0);
        __syncthreads();
    }

    // surface heads from last hidden (xh cols 0..63 hold h(59))
    if (tid < TB) {
        int r = tid;
        size_t b = b0 + r;
        float rad = p.b_sfcout[0];
        float mu0 = p.b_mu[0], mu1 = p.b_mu[1];
        float lv0 = p.b_lv[0], lv1 = p.b_lv[1];
        for (int k = 0; k < NH; k++) {
            float h = xh[r * KD2 + k];
            rad = fmaf(h, p.W_sfcout[k], rad);
            mu0 = fmaf(h, p.W_mu[k * 2 + 0], mu0);
            mu1 = fmaf(h, p.W_mu[k * 2 + 1], mu1);
            lv0 = fmaf(h, p.W_lv[k * 2 + 0], lv0);
            lv1 = fmaf(h, p.W_lv[k * 2 + 1], lv1);
        }
        float e0 = p.eps_sfc[b * 2 + 0], e1 = p.eps_sfc[b * 2 + 1];
        p.out[OFF_SFC + b * 3 + 0] = mu0 + e0 * __expf(0.5f * lv0);
        p.out[OFF_SFC + b * 3 + 1] = mu1 + e1 * __expf(0.5f * lv1);
        p.out[OFF_SFC + b * 3 + 2] = rad;
    }
}

// ===== latent + out heads; LPB levels per block =====
__global__ __launch_bounds__(256, 2)
void latent_kernel(const float* __restrict__ W_lat, const float* __restrict__ b_lat,
                   const float* __restrict__ W_out, const float* __restrict__ b_out,
                   float* __restrict__ out) {
    __shared__ float Wl[NH * 68];
    __shared__ float wout[NH * NYO + NYO];
    __shared__ float xt[TB * 68];
    __shared__ float lat[TB * 68];

    const int l0 = blockIdx.y * LPB;
    const int b0 = blockIdx.x * TB;
    const int tid = threadIdx.x;
    const int tx = tid & 63;
    const int ty = tid >> 6;

    for (int i = tid; i < NH * NH; i += 256) {
        int k = i >> 6, m = i & 63;
        Wl[m * 68 + k] = W_lat[i];
    }
    for (int i = tid; i < NH * NYO; i += 256) wout[i] = W_out[i];
    if (tid < NYO) wout[NH * NYO + tid] = b_out[tid];
    float bl = b_lat[tx];

    for (int li = 0; li < LPB; li++) {
        int l = l0 + li;
        __syncthreads();
        const float* src = g_scratch + ((size_t)l * BATCH + b0) * NH;
        for (int i = tid; i < TB * NH / 4; i += 256) {
            int r = i >> 4, q = i & 15;
            *(float4*)&xt[r * 68 + q * 4] = *(const float4*)&src[r * NH + q * 4];
        }
        __syncthreads();

        float accL[8];
#pragma unroll
        for (int u = 0; u < 8; u++) accL[u] = bl;
        for (int k = 0; k < NH; k += 4) {
            float4 wv = *(const float4*)&Wl[tx * 68 + k];
#pragma unroll
            for (int u = 0; u < 8; u++) {
                float4 xv = *(const float4*)&xt[(ty * 8 + u) * 68 + k];
                accL[u] = fmaf(xv.x, wv.x, accL[u]);
                accL[u] = fmaf(xv.y, wv.y, accL[u]);
                accL[u] = fmaf(xv.z, wv.z, accL[u]);
                accL[u] = fmaf(xv.w, wv.w, accL[u]);
            }
        }
#pragma unroll
        for (int u = 0; u < 8; u++) {
            int r = ty * 8 + u;
            size_t b = b0 + r;
            lat[r * 68 + tx] = accL[u];
            out[OFF_MEM + (b * LEV + l) * NMEM + tx] = accL[u];
        }
        __syncthreads();

        if (tid < TB * NYO) {
            int r = tid >> 2, y = tid & 3;
            float a = wout[NH * NYO + y];
            for (int m = 0; m < NH; m += 4) {
                a = fmaf(lat[r * 68 + m + 0], wout[(m + 0) * NYO + y], a);
                a = fmaf(lat[r * 68 + m + 1], wout[(m + 1) * NYO + y], a);
                a = fmaf(lat[r * 68 + m + 2], wout[(m + 2) * NYO + y], a);
                a = fmaf(lat[r * 68 + m + 3], wout[(m + 3) * NYO + y], a);
            }
            out[(size_t)(b0 + r) * (LEV * NYO) + l * NYO + y] = a;
        }
    }
}

extern "C" void kernel_launch(void* const* d_in, const int* in_sizes, int n_in,
                              void* d_out, int out_size) {
    Params p;
    p.inputs_main = (const float*)d_in[0];
    p.inputs_aux  = (const float*)d_in[1];
    p.rnn1_mem    = (const float*)d_in[2];
    p.eps1        = (const float*)d_in[3];
    p.eps2        = (const float*)d_in[4];
    p.eps_sfc     = (const float*)d_in[5];
    p.W_sfc   = (const float*)d_in[6];  p.b_sfc   = (const float*)d_in[7];
    p.W_sfc2  = (const float*)d_in[8];  p.b_sfc2  = (const float*)d_in[9];
    p.W_toa   = (const float*)d_in[10]; p.b_toa   = (const float*)d_in[11];
    p.W_toa2  = (const float*)d_in[12]; p.b_toa2  = (const float*)d_in[13];
    p.Wx1  = (const float*)d_in[14]; p.Wh1  = (const float*)d_in[15];
    p.Wxs1 = (const float*)d_in[16]; p.Whs1 = (const float*)d_in[17];
    p.Wx2  = (const float*)d_in[18]; p.Wh2  = (const float*)d_in[19];
    p.Wxs2 = (const float*)d_in[20]; p.Whs2 = (const float*)d_in[21];
    p.W_lat    = (const float*)d_in[22]; p.b_lat    = (const float*)d_in[23];
    p.W_out    = (const float*)d_in[24]; p.b_out    = (const float*)d_in[25];
    p.W_sfcout = (const float*)d_in[26]; p.b_sfcout = (const float*)d_in[27];
    p.W_mu     = (const float*)d_in[28]; p.b_mu     = (const float*)d_in[29];
    p.W_lv     = (const float*)d_in[30]; p.b_lv     = (const float*)d_in[31];
    p.out = (float*)d_out;

    cudaFuncSetAttribute(xpre_kernel, cudaFuncAttributeMaxDynamicSharedMemorySize, XPRE_SMEM);
    cudaFuncSetAttribute(rnn1_seq,    cudaFuncAttributeMaxDynamicSharedMemorySize, SEQ_SMEM);
    cudaFuncSetAttribute(rnn2_seq,    cudaFuncAttributeMaxDynamicSharedMemorySize, SEQ_SMEM);

    xpre_kernel<<<3840, 256, XPRE_SMEM>>>(0, p.inputs_main, p.rnn1_mem, p.Wx1, p.Wxs1);
    rnn1_seq<<<NBLOCKS, 256, SEQ_SMEM>>>(p);
    xpre_kernel<<<3840, 256, XPRE_SMEM>>>(1, p.inputs_main, p.rnn1_mem, p.Wx2, p.Wxs2);
    rnn2_seq<<<NBLOCKS, 256, SEQ_SMEM>>>(p);
    latent_kernel<<<dim3(NBLOCKS, LEV / LPB), 256>>>(p.W_lat, p.b_lat, p.W_out, p.b_out, p.out);
}

// round 12
// speedup vs baseline: 2.0454x; 2.0454x over previous
#include <cuda_runtime.h>
#include <math.h>
#include <stdint.h>

#define LEV 60
#define BATCH 4096
#define NXI 4
#define NH 64
#define NMEM 64
#define NSFC 17
#define NYO 4
#define NG 256
#define NWCOL 320
#define XC 320
#define KD2 68              // padded K stride (17 x 16B, odd -> conflict-free LDS.128)
#define TB2 16              // rows per seq CTA (2 CTAs/SM)
#define NB2 (BATCH / TB2)   // 256
#define LTB 32
#define LPB 5

#define OFF_SFC (BATCH * LEV * NYO)
#define OFF_MEM (OFF_SFC + BATCH * 3)

__device__ float g_scratch[(size_t)LEV * BATCH * NH];
__device__ float g_X1[(size_t)LEV * BATCH * XC];
__device__ float g_X2[(size_t)LEV * BATCH * XC];

struct Params {
    const float *inputs_main, *inputs_aux, *rnn1_mem, *eps1, *eps2, *eps_sfc;
    const float *W_sfc, *b_sfc, *W_sfc2, *b_sfc2, *W_toa, *b_toa, *W_toa2, *b_toa2;
    const float *Wx1, *Wh1, *Wxs1, *Whs1, *Wx2, *Wh2, *Wxs2, *Whs2;
    const float *W_lat, *b_lat, *W_out, *b_out, *W_sfcout, *b_sfcout;
    const float *W_mu, *b_mu, *W_lv, *b_lv;
    float *out;
};

__device__ __forceinline__ float sigmoidf_(float x) {
    return __fdividef(1.0f, 1.0f + __expf(-x));
}
__device__ __forceinline__ float tanhf_(float x) {
    float ax = fabsf(x);
    float e  = __expf(2.0f * ax);
    float t  = 1.0f - __fdividef(2.0f, e + 1.0f);
    return copysignf(t, x);
}
__device__ __forceinline__ unsigned long long fma2_(unsigned long long a,
                                                    unsigned long long b,
                                                    unsigned long long c) {
    unsigned long long d;
    asm("fma.rn.f32x2 %0, %1, %2, %3;" : "=l"(d) : "l"(a), "l"(b), "l"(c));
    return d;
}
__device__ __forceinline__ float pairsum_(unsigned long long v) {
    float lo = __int_as_float((int)(v & 0xffffffffull));
    float hi = __int_as_float((int)(v >> 32));
    return lo + hi;
}

extern __shared__ float smem[];

// =====================================================================
// xpre_simt: X = A @ [Wa|Wb] (fp32 FFMA2), persistent blocks.
// mode 0: A = [inputs_main|rnn1_mem] at level 59-s (K=68) -> g_X1
// mode 1: A = g_scratch[s]            (K=64)              -> g_X2
// grid 148 x 512 threads; W staged ONCE per block; M=64-row tiles looped.
// smem: W_s[320][68] + A_s[64][68] = 104448 B
// =====================================================================
#define XP_SMEM ((NWCOL * KD2 + 64 * KD2) * 4)

__global__ __launch_bounds__(512, 1)
void xpre_simt(int mode, int K, const float* __restrict__ im,
               const float* __restrict__ mem,
               const float* __restrict__ Wa, const float* __restrict__ Wb) {
    float* W_s = smem;                 // [320][KD2]
    float* A_s = smem + NWCOL * KD2;   // [64][KD2]
    const int tid = threadIdx.x;
    const int tx = tid & 63;
    const int ty = tid >> 6;           // 0..7, 8 rows each
    float* Xout = mode ? g_X2 : g_X1;

    // stage W transposed (coalesced global reads; one-time 4-way STS conflicts)
    for (int idx = tid; idx < NWCOL * KD2; idx += 512) {
        int k = idx / NWCOL, j = idx % NWCOL;
        float v = 0.f;
        if (k < K) v = (j < NG) ? Wa[(size_t)k * NG + j] : Wb[(size_t)k * NH + (j - NG)];
        W_s[j * KD2 + k] = v;
    }
    __syncthreads();

    for (int t = blockIdx.x; t < 3840; t += gridDim.x) {
        int s = t >> 6, b0 = (t & 63) * 64;
        // stage A tile (64 x K, zero-padded to KD2)
        for (int idx = tid; idx < 64 * KD2; idx += 512) {
            int r = idx / KD2, k = idx % KD2;
            float v = 0.f;
            if (k < K) {
                if (mode == 0) {
                    int b = b0 + r, l = LEV - 1 - s;
                    v = (k < NXI) ? im[((size_t)b * LEV + l) * NXI + k]
                                  : mem[((size_t)b * LEV + l) * NMEM + (k - NXI)];
                } else {
                    v = g_scratch[((size_t)s * BATCH + b0 + r) * NH + k];
                }
            }
            A_s[r * KD2 + k] = v;
        }
        __syncthreads();

        unsigned long long acc[8][5];
#pragma unroll
        for (int u = 0; u < 8; u++)
#pragma unroll
            for (int c = 0; c < 5; c++) acc[u][c] = 0ull;

#pragma unroll 1
        for (int kq = 0; kq < KD2 / 4; kq++) {
            ulonglong2 wv[5];
#pragma unroll
            for (int c = 0; c < 5; c++)
                wv[c] = *(const ulonglong2*)&W_s[(c * 64 + tx) * KD2 + kq * 4];
#pragma unroll
            for (int u = 0; u < 8; u++) {
                ulonglong2 xv = *(const ulonglong2*)&A_s[(ty * 8 + u) * KD2 + kq * 4];
#pragma unroll
                for (int c = 0; c < 5; c++) {
                    acc[u][c] = fma2_(xv.x, wv[c].x, acc[u][c]);
                    acc[u][c] = fma2_(xv.y, wv[c].y, acc[u][c]);
                }
            }
        }
        size_t rb = (size_t)s * BATCH + b0;
#pragma unroll
        for (int u = 0; u < 8; u++)
#pragma unroll
            for (int c = 0; c < 5; c++)
                Xout[(rb + ty * 8 + u) * XC + c * 64 + tx] = pairsum_(acc[u][c]);
        __syncthreads();   // A_s reused next tile
    }
}

// =====================================================================
// Sequential h-only recurrence, K=64, TB2=16 rows, 2 CTAs/SM
// smem: W_s[320][68] + xh[16][68] + gacc[16][320] = 111872 B
// =====================================================================
#define SM2_W    (NWCOL * KD2)
#define SM2_XH   (TB2 * KD2)
#define SM2_GACC (TB2 * NWCOL)
#define SEQ_SMEM ((SM2_W + SM2_XH + SM2_GACC) * 4)

__device__ __forceinline__ void gemm16_(const float* __restrict__ W_s,
                                        const float* __restrict__ xh,
                                        float* __restrict__ gacc,
                                        int tx, int ty) {
    unsigned long long acc[4][5];
#pragma unroll
    for (int u = 0; u < 4; u++)
#pragma unroll
        for (int c = 0; c < 5; c++) acc[u][c] = 0ull;
#pragma unroll 1
    for (int kq = 0; kq < 16; kq++) {
        ulonglong2 wv[5];
#pragma unroll
        for (int c = 0; c < 5; c++)
            wv[c] = *(const ulonglong2*)&W_s[(c * 64 + tx) * KD2 + kq * 4];
#pragma unroll
        for (int u = 0; u < 4; u++) {
            ulonglong2 xv = *(const ulonglong2*)&xh[(ty * 4 + u) * KD2 + kq * 4];
#pragma unroll
            for (int c = 0; c < 5; c++) {
                acc[u][c] = fma2_(xv.x, wv[c].x, acc[u][c]);
                acc[u][c] = fma2_(xv.y, wv[c].y, acc[u][c]);
            }
        }
    }
#pragma unroll
    for (int u = 0; u < 4; u++)
#pragma unroll
        for (int c = 0; c < 5; c++)
            gacc[(ty * 4 + u) * NWCOL + c * 64 + tx] = pairsum_(acc[u][c]);
}

// pointwise for 4 elems (row pr, cols pj0..pj0+3); Xr/ge prefetched in registers
__device__ __forceinline__ void pointwise16_(float* __restrict__ xh,
                                             const float* __restrict__ gacc,
                                             float* __restrict__ c_reg,
                                             int pr, int pj0,
                                             const float* __restrict__ Xr,
                                             const float* __restrict__ ge,
                                             float* __restrict__ hout_ptr) {
    const float* g = gacc + pr * NWCOL + pj0;
    float gi[4], gf[4], gg[4], go[4], gv[4];
    *(float4*)&gi[0] = *(const float4*)(g);
    *(float4*)&gf[0] = *(const float4*)(g + 64);
    *(float4*)&gg[0] = *(const float4*)(g + 128);
    *(float4*)&go[0] = *(const float4*)(g + 192);
    *(float4*)&gv[0] = *(const float4*)(g + 256);
    float hs[4];
#pragma unroll
    for (int u = 0; u < 4; u++) {
        float iv = sigmoidf_(gi[u] + Xr[u]);
        float fv = sigmoidf_(gf[u] + Xr[4 + u]);
        float gt = tanhf_(gg[u] + Xr[8 + u]);
        float ov = sigmoidf_(go[u] + Xr[12 + u]);
        float cc = fv * c_reg[u] + iv * gt;
        c_reg[u] = cc;
        float h  = ov * tanhf_(cc) + ge[u] * __expf(0.5f * (gv[u] + Xr[16 + u]));
        xh[pr * KD2 + pj0 + u] = h;
        hs[u] = h;
    }
    *(float4*)(hout_ptr) = *(const float4*)&hs[0];
}

__device__ __forceinline__ void stage_Wh_(float* __restrict__ W_s,
                                          const float* __restrict__ Wh,
                                          const float* __restrict__ Whs, int tid) {
    // coalesced global reads (j fastest), transposed STS
    for (int idx = tid; idx < NWCOL * KD2; idx += 256) {
        int k = idx / NWCOL, j = idx % NWCOL;
        float v = 0.f;
        if (k < NH) v = (j < NG) ? Wh[(size_t)k * NG + j] : Whs[(size_t)k * NH + (j - NG)];
        W_s[j * KD2 + k] = v;
    }
}

__global__ __launch_bounds__(256, 2)
void rnn1_seq(Params p) {
    const int tid = threadIdx.x;
    const int b0  = blockIdx.x * TB2;
    float* W_s  = smem;
    float* xh   = smem + SM2_W;
    float* gacc = xh + SM2_XH;
    const int pr = tid >> 4, pj0 = (tid & 15) * 4;
    const int tx = tid & 63, ty = tid >> 6;
    float c_reg[4];

    stage_Wh_(W_s, p.Wh1, p.Whs1, tid);
    {   // h0/c0 from surface MLPs
        const float* auxrow = p.inputs_aux + (size_t)(b0 + pr) * NSFC;
#pragma unroll
        for (int u = 0; u < 4; u++) {
            int j = pj0 + u;
            float ah = p.b_sfc[j], ac = p.b_sfc2[j];
            for (int k = 0; k < NSFC; k++) {
                float a = auxrow[k];
                ah = fmaf(a, p.W_sfc[k * NH + j], ah);
                ac = fmaf(a, p.W_sfc2[k * NH + j], ac);
            }
            xh[pr * KD2 + j] = tanhf_(ah);
            c_reg[u] = tanhf_(ac);
        }
    }
    __syncthreads();

    for (int s = 0; s < LEV; s++) {
        float Xr[20], ge[4];
        {
            const float* xp = g_X1 + ((size_t)s * BATCH + b0 + pr) * XC + pj0;
#pragma unroll
            for (int c = 0; c < 5; c++)
                *(float4*)&Xr[c * 4] = *(const float4*)(xp + c * 64);
            *(float4*)&ge[0] = *(const float4*)(p.eps1 + ((size_t)s * BATCH + b0 + pr) * NH + pj0);
        }
        gemm16_(W_s, xh, gacc, tx, ty);
        __syncthreads();
        pointwise16_(xh, gacc, c_reg, pr, pj0, Xr, ge,
                     g_scratch + ((size_t)(LEV - 1 - s) * BATCH + b0 + pr) * NH + pj0);
        __syncthreads();
    }
}

__global__ __launch_bounds__(256, 2)
void rnn2_seq(Params p) {
    const int tid = threadIdx.x;
    const int b0  = blockIdx.x * TB2;
    float* W_s  = smem;
    float* xh   = smem + SM2_W;
    float* gacc = xh + SM2_XH;
    const int pr = tid >> 4, pj0 = (tid & 15) * 4;
    const int tx = tid & 63, ty = tid >> 6;
    float c_reg[4];

    stage_Wh_(W_s, p.Wh2, p.Whs2, tid);
    {   // h0/c0 from TOA MLPs (aux cols 1 and 6)
        float x0 = p.inputs_aux[(size_t)(b0 + pr) * NSFC + 1];
        float x1 = p.inputs_aux[(size_t)(b0 + pr) * NSFC + 6];
#pragma unroll
        for (int u = 0; u < 4; u++) {
            int j = pj0 + u;
            float ah = fmaf(x0, p.W_toa[j],  fmaf(x1, p.W_toa[NH + j],  p.b_toa[j]));
            float ac = fmaf(x0, p.W_toa2[j], fmaf(x1, p.W_toa2[NH + j], p.b_toa2[j]));
            xh[pr * KD2 + j] = tanhf_(ah);
            c_reg[u] = tanhf_(ac);
        }
    }
    __syncthreads();

    for (int s = 0; s < LEV; s++) {
        float Xr[20], ge[4];
        {
            const float* xp = g_X2 + ((size_t)s * BATCH + b0 + pr) * XC + pj0;
#pragma unroll
            for (int c = 0; c < 5; c++)
                *(float4*)&Xr[c * 4] = *(const float4*)(xp + c * 64);
            *(float4*)&ge[0] = *(const float4*)(p.eps2 + ((size_t)s * BATCH + b0 + pr) * NH + pj0);
        }
        gemm16_(W_s, xh, gacc, tx, ty);
        __syncthreads();
        pointwise16_(xh, gacc, c_reg, pr, pj0, Xr, ge,
                     g_scratch + ((size_t)s * BATCH + b0 + pr) * NH + pj0);
        __syncthreads();
    }

    // surface heads from last hidden (xh rows 0..15, cols 0..63)
    if (tid < TB2) {
        int r = tid;
        size_t b = b0 + r;
        float rad = p.b_sfcout[0];
        float mu0 = p.b_mu[0], mu1 = p.b_mu[1];
        float lv0 = p.b_lv[0], lv1 = p.b_lv[1];
        for (int k = 0; k < NH; k++) {
            float h = xh[r * KD2 + k];
            rad = fmaf(h, p.W_sfcout[k], rad);
            mu0 = fmaf(h, p.W_mu[k * 2 + 0], mu0);
            mu1 = fmaf(h, p.W_mu[k * 2 + 1], mu1);
            lv0 = fmaf(h, p.W_lv[k * 2 + 0], lv0);
            lv1 = fmaf(h, p.W_lv[k * 2 + 1], lv1);
        }
        float e0 = p.eps_sfc[b * 2 + 0], e1 = p.eps_sfc[b * 2 + 1];
        p.out[OFF_SFC + b * 3 + 0] = mu0 + e0 * __expf(0.5f * lv0);
        p.out[OFF_SFC + b * 3 + 1] = mu1 + e1 * __expf(0.5f * lv1);
        p.out[OFF_SFC + b * 3 + 2] = rad;
    }
}

// ===== latent + out heads; LPB levels per block, occupancy 4, fma2 =====
__global__ __launch_bounds__(256, 4)
void latent_kernel(const float* __restrict__ W_lat, const float* __restrict__ b_lat,
                   const float* __restrict__ W_out, const float* __restrict__ b_out,
                   float* __restrict__ out) {
    __shared__ float Wl[NH * KD2];
    __shared__ float wout[NH * NYO + NYO];
    __shared__ float xt[LTB * KD2];
    __shared__ float lat[LTB * KD2];

    const int l0 = blockIdx.y * LPB;
    const int b0 = blockIdx.x * LTB;
    const int tid = threadIdx.x;
    const int tx = tid & 63;
    const int ty = tid >> 6;

    for (int i = tid; i < NH * NH; i += 256) {
        int k = i >> 6, m = i & 63;
        Wl[m * KD2 + k] = W_lat[i];
    }
    for (int i = tid; i < NH * NYO; i += 256) wout[i] = W_out[i];
    if (tid < NYO) wout[NH * NYO + tid] = b_out[tid];
    float bl = b_lat[tx];

    for (int li = 0; li < LPB; li++) {
        int l = l0 + li;
        __syncthreads();
        const float* src = g_scratch + ((size_t)l * BATCH + b0) * NH;
        for (int i = tid; i < LTB * NH / 4; i += 256) {
            int r = i >> 4, q = i & 15;
            *(float4*)&xt[r * KD2 + q * 4] = *(const float4*)&src[r * NH + q * 4];
        }
        __syncthreads();

        unsigned long long accL[8];
#pragma unroll
        for (int u = 0; u < 8; u++) accL[u] = 0ull;
#pragma unroll 1
        for (int kq = 0; kq < 16; kq++) {
            ulonglong2 wv = *(const ulonglong2*)&Wl[tx * KD2 + kq * 4];
#pragma unroll
            for (int u = 0; u < 8; u++) {
                ulonglong2 xv = *(const ulonglong2*)&xt[(ty * 8 + u) * KD2 + kq * 4];
                accL[u] = fma2_(xv.x, wv.x, accL[u]);
                accL[u] = fma2_(xv.y, wv.y, accL[u]);
            }
        }
#pragma unroll
        for (int u = 0; u < 8; u++) {
            int r = ty * 8 + u;
            size_t b = b0 + r;
            float v = pairsum_(accL[u]) + bl;
            lat[r * KD2 + tx] = v;
            out[OFF_MEM + (b * LEV + l) * NMEM + tx] = v;
        }
        __syncthreads();

        if (tid < LTB * NYO) {
            int r = tid >> 2, y = tid & 3;
            float a = wout[NH * NYO + y];
            for (int m = 0; m < NH; m += 4) {
                a = fmaf(lat[r * KD2 + m + 0], wout[(m + 0) * NYO + y], a);
                a = fmaf(lat[r * KD2 + m + 1], wout[(m + 1) * NYO + y], a);
                a = fmaf(lat[r * KD2 + m + 2], wout[(m + 2) * NYO + y], a);
                a = fmaf(lat[r * KD2 + m + 3], wout[(m + 3) * NYO + y], a);
            }
            out[(size_t)(b0 + r) * (LEV * NYO) + l * NYO + y] = a;
        }
    }
}

extern "C" void kernel_launch(void* const* d_in, const int* in_sizes, int n_in,
                              void* d_out, int out_size) {
    Params p;
    p.inputs_main = (const float*)d_in[0];
    p.inputs_aux  = (const float*)d_in[1];
    p.rnn1_mem    = (const float*)d_in[2];
    p.eps1        = (const float*)d_in[3];
    p.eps2        = (const float*)d_in[4];
    p.eps_sfc     = (const float*)d_in[5];
    p.W_sfc   = (const float*)d_in[6];  p.b_sfc   = (const float*)d_in[7];
    p.W_sfc2  = (const float*)d_in[8];  p.b_sfc2  = (const float*)d_in[9];
    p.W_toa   = (const float*)d_in[10]; p.b_toa   = (const float*)d_in[11];
    p.W_toa2  = (const float*)d_in[12]; p.b_toa2  = (const float*)d_in[13];
    p.Wx1  = (const float*)d_in[14]; p.Wh1  = (const float*)d_in[15];
    p.Wxs1 = (const float*)d_in[16]; p.Whs1 = (const float*)d_in[17];
    p.Wx2  = (const float*)d_in[18]; p.Wh2  = (const float*)d_in[19];
    p.Wxs2 = (const float*)d_in[20]; p.Whs2 = (const float*)d_in[21];
    p.W_lat    = (const float*)d_in[22]; p.b_lat    = (const float*)d_in[23];
    p.W_out    = (const float*)d_in[24]; p.b_out    = (const float*)d_in[25];
    p.W_sfcout = (const float*)d_in[26]; p.b_sfcout = (const float*)d_in[27];
    p.W_mu     = (const float*)d_in[28]; p.b_mu     = (const float*)d_in[29];
    p.W_lv     = (const float*)d_in[30]; p.b_lv     = (const float*)d_in[31];
    p.out = (float*)d_out;

    cudaFuncSetAttribute(xpre_simt, cudaFuncAttributeMaxDynamicSharedMemorySize, XP_SMEM);
    cudaFuncSetAttribute(rnn1_seq,  cudaFuncAttributeMaxDynamicSharedMemorySize, SEQ_SMEM);
    cudaFuncSetAttribute(rnn2_seq,  cudaFuncAttributeMaxDynamicSharedMemorySize, SEQ_SMEM);

    xpre_simt<<<148, 512, XP_SMEM>>>(0, 68, p.inputs_main, p.rnn1_mem, p.Wx1, p.Wxs1);
    rnn1_seq<<<NB2, 256, SEQ_SMEM>>>(p);
    xpre_simt<<<148, 512, XP_SMEM>>>(1, 64, p.inputs_main, p.rnn1_mem, p.Wx2, p.Wxs2);
    rnn2_seq<<<NB2, 256, SEQ_SMEM>>>(p);
    latent_kernel<<<dim3(BATCH / LTB, LEV / LPB), 256>>>(p.W_lat, p.b_lat, p.W_out, p.b_out, p.out);
}

// round 14
// speedup vs baseline: 2.2734x; 1.1115x over previous
#include <cuda_runtime.h>
#include <math.h>
#include <stdint.h>

#define LEV 60
#define BATCH 4096
#define NXI 4
#define NH 64
#define NMEM 64
#define NSFC 17
#define NYO 4
#define NG 256
#define NWCOL 320
#define XC 320
#define KD2 68              // padded K stride
#define TB2 16              // rows per seq CTA (2 CTAs/SM)
#define NB2 (BATCH / TB2)   // 256
#define LTB 32
#define LPB 5

#define OFF_SFC (BATCH * LEV * NYO)
#define OFF_MEM (OFF_SFC + BATCH * 3)

__device__ float g_scratch[(size_t)LEV * BATCH * NH];
__device__ float g_X1[(size_t)LEV * BATCH * XC];
__device__ float g_X2[(size_t)LEV * BATCH * XC];

struct Params {
    const float *inputs_main, *inputs_aux, *rnn1_mem, *eps1, *eps2, *eps_sfc;
    const float *W_sfc, *b_sfc, *W_sfc2, *b_sfc2, *W_toa, *b_toa, *W_toa2, *b_toa2;
    const float *Wx1, *Wh1, *Wxs1, *Whs1, *Wx2, *Wh2, *Wxs2, *Whs2;
    const float *W_lat, *b_lat, *W_out, *b_out, *W_sfcout, *b_sfcout;
    const float *W_mu, *b_mu, *W_lv, *b_lv;
    float *out;
};

__device__ __forceinline__ float sigmoidf_(float x) {
    return __fdividef(1.0f, 1.0f + __expf(-x));
}
__device__ __forceinline__ float tanhf_(float x) {
    float ax = fabsf(x);
    float e  = __expf(2.0f * ax);
    float t  = 1.0f - __fdividef(2.0f, e + 1.0f);
    return copysignf(t, x);
}
__device__ __forceinline__ unsigned long long fma2_(unsigned long long a,
                                                    unsigned long long b,
                                                    unsigned long long c) {
    unsigned long long d;
    asm("fma.rn.f32x2 %0, %1, %2, %3;" : "=l"(d) : "l"(a), "l"(b), "l"(c));
    return d;
}
__device__ __forceinline__ float pairsum_(unsigned long long v) {
    float lo = __int_as_float((int)(v & 0xffffffffull));
    float hi = __int_as_float((int)(v >> 32));
    return lo + hi;
}

extern __shared__ float smem[];

// =====================================================================
// xpre_simt: X = A @ [Wa|Wb] (FFMA2), persistent, A double-buffered.
// mode 0: A = [inputs_main|rnn1_mem] at level 59-s (K=68) -> g_X1
// mode 1: A = g_scratch[s]            (K=64)              -> g_X2
// grid 148 x 512 thr; M=64-row tiles, 3840 total, ~26/block.
// smem: W_s[320][68] + A_s[2][64][68] = 121856 B
// =====================================================================
#define XP_A (64 * KD2)
#define XP_SMEM ((NWCOL * KD2 + 2 * XP_A) * 4)
#define NPREF 9             // ceil(64*68/512)

__device__ __forceinline__ void xpre_fetch_(int mode, int K, int t,
                                            const float* __restrict__ im,
                                            const float* __restrict__ mem,
                                            float* __restrict__ pref, int tid) {
    int s = t >> 6, b0 = (t & 63) * 64;
    int n = 0;
    for (int idx = tid; idx < XP_A; idx += 512, n++) {
        int r = idx / KD2, k = idx % KD2;
        float v = 0.f;
        if (k < K) {
            if (mode == 0) {
                int b = b0 + r, l = LEV - 1 - s;
                v = (k < NXI) ? im[((size_t)b * LEV + l) * NXI + k]
                              : mem[((size_t)b * LEV + l) * NMEM + (k - NXI)];
            } else {
                v = g_scratch[((size_t)s * BATCH + b0 + r) * NH + k];
            }
        }
        pref[n] = v;
    }
}

__global__ __launch_bounds__(512, 1)
void xpre_simt(int mode, int K, const float* __restrict__ im,
               const float* __restrict__ mem,
               const float* __restrict__ Wa, const float* __restrict__ Wb) {
    float* W_s = smem;                     // [320][KD2]
    float* A_b = smem + NWCOL * KD2;       // [2][64][KD2]
    const int tid = threadIdx.x;
    const int tx = tid & 63;
    const int ty = tid >> 6;               // 0..7, 8 rows each
    float* Xout = mode ? g_X2 : g_X1;

    for (int idx = tid; idx < NWCOL * KD2; idx += 512) {
        int k = idx / NWCOL, j = idx % NWCOL;
        float v = 0.f;
        if (k < K) v = (j < NG) ? Wa[(size_t)k * NG + j] : Wb[(size_t)k * NH + (j - NG)];
        W_s[j * KD2 + k] = v;
    }

    const int t0 = blockIdx.x;
    float pref[NPREF];
    // stage first tile
    xpre_fetch_(mode, K, t0, im, mem, pref, tid);
    {
        int n = 0;
        for (int idx = tid; idx < XP_A; idx += 512, n++) A_b[idx] = pref[n];
    }
    __syncthreads();

    int buf = 0;
    for (int t = t0; t < 3840; t += 148) {
        int tn = t + 148;
        if (tn < 3840) xpre_fetch_(mode, K, tn, im, mem, pref, tid);

        const float* A_s = A_b + buf * XP_A;
        unsigned long long acc[8][5];
#pragma unroll
        for (int u = 0; u < 8; u++)
#pragma unroll
            for (int c = 0; c < 5; c++) acc[u][c] = 0ull;

#pragma unroll 1
        for (int kq = 0; kq < KD2 / 4; kq++) {
            ulonglong2 wv[5];
#pragma unroll
            for (int c = 0; c < 5; c++)
                wv[c] = *(const ulonglong2*)&W_s[(c * 64 + tx) * KD2 + kq * 4];
#pragma unroll
            for (int u = 0; u < 8; u++) {
                ulonglong2 xv = *(const ulonglong2*)&A_s[(ty * 8 + u) * KD2 + kq * 4];
#pragma unroll
                for (int c = 0; c < 5; c++) {
                    acc[u][c] = fma2_(xv.x, wv[c].x, acc[u][c]);
                    acc[u][c] = fma2_(xv.y, wv[c].y, acc[u][c]);
                }
            }
        }
        {
            int s = t >> 6, b0 = (t & 63) * 64;
            size_t rb = (size_t)s * BATCH + b0;
#pragma unroll
            for (int u = 0; u < 8; u++)
#pragma unroll
                for (int c = 0; c < 5; c++)
                    Xout[(rb + ty * 8 + u) * XC + c * 64 + tx] = pairsum_(acc[u][c]);
        }
        // commit prefetched tile to alternate buffer
        if (tn < 3840) {
            float* An = A_b + (buf ^ 1) * XP_A;
            int n = 0;
            for (int idx = tid; idx < XP_A; idx += 512, n++) An[idx] = pref[n];
        }
        __syncthreads();
        buf ^= 1;
    }
}

// =====================================================================
// Sequential h-only recurrence, K=64, TB2=16, 2 CTAs/SM.
// Register pointwise (no gacc), double-buffered xh, 1 sync/step.
// thread (tx = tid&63, ty = tid>>6) owns rows {ty*4+u} x col tx (5 gates).
// smem: W_s[320][68] + xh[2][16][68] = 95744 B
// =====================================================================
#define XH1 (TB2 * KD2)
#define SEQ_SMEM ((NWCOL * KD2 + 2 * XH1) * 4)

__device__ __forceinline__ void stage_Wh_(float* __restrict__ W_s,
                                          const float* __restrict__ Wh,
                                          const float* __restrict__ Whs, int tid) {
    for (int idx = tid; idx < NWCOL * KD2; idx += 256) {
        int k = idx / NWCOL, j = idx % NWCOL;
        float v = 0.f;
        if (k < NH) v = (j < NG) ? Wh[(size_t)k * NG + j] : Whs[(size_t)k * NH + (j - NG)];
        W_s[j * KD2 + k] = v;
    }
}

// One LSTM step: GEMM on cur (K=64) + pointwise in registers -> nxt + scratch
__device__ __forceinline__ void seq_step_(const float* __restrict__ W_s,
                                          const float* __restrict__ cur,
                                          float* __restrict__ nxt,
                                          float* __restrict__ c_reg,
                                          int tx, int ty,
                                          const float* __restrict__ xp0,   // X row base (row ty*4)
                                          const float* __restrict__ ep0,   // eps row base
                                          float* __restrict__ sp0) {       // scratch row base
    // prefetch X and eps (latency hidden under GEMM)
    float Xr[20], ge[4];
#pragma unroll
    for (int u = 0; u < 4; u++) {
#pragma unroll
        for (int c = 0; c < 5; c++)
            Xr[u * 5 + c] = xp0[(size_t)u * XC + c * 64 + tx];
        ge[u] = ep0[(size_t)u * NH + tx];
    }

    unsigned long long acc[4][5];
#pragma unroll
    for (int u = 0; u < 4; u++)
#pragma unroll
        for (int c = 0; c < 5; c++) acc[u][c] = 0ull;
#pragma unroll 1
    for (int kq = 0; kq < 16; kq++) {
        ulonglong2 wv[5];
#pragma unroll
        for (int c = 0; c < 5; c++)
            wv[c] = *(const ulonglong2*)&W_s[(c * 64 + tx) * KD2 + kq * 4];
#pragma unroll
        for (int u = 0; u < 4; u++) {
            ulonglong2 xv = *(const ulonglong2*)&cur[(ty * 4 + u) * KD2 + kq * 4];
#pragma unroll
            for (int c = 0; c < 5; c++) {
                acc[u][c] = fma2_(xv.x, wv[c].x, acc[u][c]);
                acc[u][c] = fma2_(xv.y, wv[c].y, acc[u][c]);
            }
        }
    }
#pragma unroll
    for (int u = 0; u < 4; u++) {
        int row = ty * 4 + u;
        float iv = sigmoidf_(pairsum_(acc[u][0]) + Xr[u * 5 + 0]);
        float fv = sigmoidf_(pairsum_(acc[u][1]) + Xr[u * 5 + 1]);
        float gt = tanhf_(pairsum_(acc[u][2]) + Xr[u * 5 + 2]);
        float ov = sigmoidf_(pairsum_(acc[u][3]) + Xr[u * 5 + 3]);
        float lv = pairsum_(acc[u][4]) + Xr[u * 5 + 4];
        float cc = fv * c_reg[u] + iv * gt;
        c_reg[u] = cc;
        float h  = ov * tanhf_(cc) + ge[u] * __expf(0.5f * lv);
        nxt[row * KD2 + tx] = h;
        sp0[(size_t)u * NH + tx] = h;
    }
}

__global__ __launch_bounds__(256, 2)
void rnn1_seq(Params p) {
    const int tid = threadIdx.x;
    const int b0  = blockIdx.x * TB2;
    float* W_s = smem;
    float* xh  = smem + NWCOL * KD2;   // [2][16][KD2]
    const int tx = tid & 63, ty = tid >> 6;
    float c_reg[4];

    stage_Wh_(W_s, p.Wh1, p.Whs1, tid);
#pragma unroll
    for (int u = 0; u < 4; u++) {
        int row = ty * 4 + u;
        const float* auxrow = p.inputs_aux + (size_t)(b0 + row) * NSFC;
        float ah = p.b_sfc[tx], ac = p.b_sfc2[tx];
        for (int k = 0; k < NSFC; k++) {
            float a = auxrow[k];
            ah = fmaf(a, p.W_sfc[k * NH + tx], ah);
            ac = fmaf(a, p.W_sfc2[k * NH + tx], ac);
        }
        xh[row * KD2 + tx] = tanhf_(ah);
        c_reg[u] = tanhf_(ac);
    }
    __syncthreads();

    const float* xp0 = g_X1 + (size_t)(b0 + ty * 4) * XC;
    const float* ep0 = p.eps1 + (size_t)(b0 + ty * 4) * NH;
    float* sp0 = g_scratch + ((size_t)(LEV - 1) * BATCH + b0 + ty * 4) * NH;

    for (int s = 0; s < LEV; s++) {
        const float* cur = xh + (s & 1) * XH1;
        float* nxt = xh + ((s + 1) & 1) * XH1;
        seq_step_(W_s, cur, nxt, c_reg, tx, ty, xp0, ep0, sp0);
        xp0 += (size_t)BATCH * XC;
        ep0 += (size_t)BATCH * NH;
        sp0 -= (size_t)BATCH * NH;
        __syncthreads();
    }
}

__global__ __launch_bounds__(256, 2)
void rnn2_seq(Params p) {
    const int tid = threadIdx.x;
    const int b0  = blockIdx.x * TB2;
    float* W_s = smem;
    float* xh  = smem + NWCOL * KD2;
    const int tx = tid & 63, ty = tid >> 6;
    float c_reg[4];

    stage_Wh_(W_s, p.Wh2, p.Whs2, tid);
#pragma unroll
    for (int u = 0; u < 4; u++) {
        int row = ty * 4 + u;
        float x0 = p.inputs_aux[(size_t)(b0 + row) * NSFC + 1];
        float x1 = p.inputs_aux[(size_t)(b0 + row) * NSFC + 6];
        float ah = fmaf(x0, p.W_toa[tx],  fmaf(x1, p.W_toa[NH + tx],  p.b_toa[tx]));
        float ac = fmaf(x0, p.W_toa2[tx], fmaf(x1, p.W_toa2[NH + tx], p.b_toa2[tx]));
        xh[row * KD2 + tx] = tanhf_(ah);
        c_reg[u] = tanhf_(ac);
    }
    __syncthreads();

    const float* xp0 = g_X2 + (size_t)(b0 + ty * 4) * XC;
    const float* ep0 = p.eps2 + (size_t)(b0 + ty * 4) * NH;
    float* sp0 = g_scratch + (size_t)(b0 + ty * 4) * NH;

    for (int s = 0; s < LEV; s++) {
        const float* cur = xh + (s & 1) * XH1;
        float* nxt = xh + ((s + 1) & 1) * XH1;
        seq_step_(W_s, cur, nxt, c_reg, tx, ty, xp0, ep0, sp0);
        xp0 += (size_t)BATCH * XC;
        ep0 += (size_t)BATCH * NH;
        sp0 += (size_t)BATCH * NH;
        __syncthreads();
    }

    // surface heads from last hidden: step 59 wrote xh buffer (60&1)=0
    if (tid < TB2) {
        const float* hl = xh;            // buffer 0
        int r = tid;
        size_t b = b0 + r;
        float rad = p.b_sfcout[0];
        float mu0 = p.b_mu[0], mu1 = p.b_mu[1];
        float lv0 = p.b_lv[0], lv1 = p.b_lv[1];
        for (int k = 0; k < NH; k++) {
            float h = hl[r * KD2 + k];
            rad = fmaf(h, p.W_sfcout[k], rad);
            mu0 = fmaf(h, p.W_mu[k * 2 + 0], mu0);
            mu1 = fmaf(h, p.W_mu[k * 2 + 1], mu1);
            lv0 = fmaf(h, p.W_lv[k * 2 + 0], lv0);
            lv1 = fmaf(h, p.W_lv[k * 2 + 1], lv1);
        }
        float e0 = p.eps_sfc[b * 2 + 0], e1 = p.eps_sfc[b * 2 + 1];
        p.out[OFF_SFC + b * 3 + 0] = mu0 + e0 * __expf(0.5f * lv0);
        p.out[OFF_SFC + b * 3 + 1] = mu1 + e1 * __expf(0.5f * lv1);
        p.out[OFF_SFC + b * 3 + 2] = rad;
    }
}

// ===== latent + out heads; LPB levels per block, occ 4, fma2 =====
__global__ __launch_bounds__(256, 4)
void latent_kernel(const float* __restrict__ W_lat, const float* __restrict__ b_lat,
                   const float* __restrict__ W_out, const float* __restrict__ b_out,
                   float* __restrict__ out) {
    __shared__ float Wl[NH * KD2];
    __shared__ float wout[NH * NYO + NYO];
    __shared__ float xt[LTB * KD2];
    __shared__ float lat[LTB * KD2];

    const int l0 = blockIdx.y * LPB;
    const int b0 = blockIdx.x * LTB;
    const int tid = threadIdx.x;
    const int tx = tid & 63;
    const int ty = tid >> 6;

    for (int i = tid; i < NH * NH; i += 256) {
        int k = i >> 6, m = i & 63;
        Wl[m * KD2 + k] = W_lat[i];
    }
    for (int i = tid; i < NH * NYO; i += 256) wout[i] = W_out[i];
    if (tid < NYO) wout[NH * NYO + tid] = b_out[tid];
    float bl = b_lat[tx];

    for (int li = 0; li < LPB; li++) {
        int l = l0 + li;
        __syncthreads();
        const float* src = g_scratch + ((size_t)l * BATCH + b0) * NH;
        for (int i = tid; i < LTB * NH / 4; i += 256) {
            int r = i >> 4, q = i & 15;
            *(float4*)&xt[r * KD2 + q * 4] = *(const float4*)&src[r * NH + q * 4];
        }
        __syncthreads();

        unsigned long long accL[8];
#pragma unroll
        for (int u = 0; u < 8; u++) accL[u] = 0ull;
#pragma unroll 1
        for (int kq = 0; kq < 16; kq++) {
            ulonglong2 wv = *(const ulonglong2*)&Wl[tx * KD2 + kq * 4];
#pragma unroll
            for (int u = 0; u < 8; u++) {
                ulonglong2 xv = *(const ulonglong2*)&xt[(ty * 8 + u) * KD2 + kq * 4];
                accL[u] = fma2_(xv.x, wv.x, accL[u]);
                accL[u] = fma2_(xv.y, wv.y, accL[u]);
            }
        }
#pragma unroll
        for (int u = 0; u < 8; u++) {
            int r = ty * 8 + u;
            size_t b = b0 + r;
            float v = pairsum_(accL[u]) + bl;
            lat[r * KD2 + tx] = v;
            out[OFF_MEM + (b * LEV + l) * NMEM + tx] = v;
        }
        __syncthreads();

        if (tid < LTB * NYO) {
            int r = tid >> 2, y = tid & 3;
            float a = wout[NH * NYO + y];
            for (int m = 0; m < NH; m += 4) {
                a = fmaf(lat[r * KD2 + m + 0], wout[(m + 0) * NYO + y], a);
                a = fmaf(lat[r * KD2 + m + 1], wout[(m + 1) * NYO + y], a);
                a = fmaf(lat[r * KD2 + m + 2], wout[(m + 2) * NYO + y], a);
                a = fmaf(lat[r * KD2 + m + 3], wout[(m + 3) * NYO + y], a);
            }
            out[(size_t)(b0 + r) * (LEV * NYO) + l * NYO + y] = a;
        }
    }
}

extern "C" void kernel_launch(void* const* d_in, const int* in_sizes, int n_in,
                              void* d_out, int out_size) {
    Params p;
    p.inputs_main = (const float*)d_in[0];
    p.inputs_aux  = (const float*)d_in[1];
    p.rnn1_mem    = (const float*)d_in[2];
    p.eps1        = (const float*)d_in[3];
    p.eps2        = (const float*)d_in[4];
    p.eps_sfc     = (const float*)d_in[5];
    p.W_sfc   = (const float*)d_in[6];  p.b_sfc   = (const float*)d_in[7];
    p.W_sfc2  = (const float*)d_in[8];  p.b_sfc2  = (const float*)d_in[9];
    p.W_toa   = (const float*)d_in[10]; p.b_toa   = (const float*)d_in[11];
    p.W_toa2  = (const float*)d_in[12]; p.b_toa2  = (const float*)d_in[13];
    p.Wx1  = (const float*)d_in[14]; p.Wh1  = (const float*)d_in[15];
    p.Wxs1 = (const float*)d_in[16]; p.Whs1 = (const float*)d_in[17];
    p.Wx2  = (const float*)d_in[18]; p.Wh2  = (const float*)d_in[19];
    p.Wxs2 = (const float*)d_in[20]; p.Whs2 = (const float*)d_in[21];
    p.W_lat    = (const float*)d_in[22]; p.b_lat    = (const float*)d_in[23];
    p.W_out    = (const float*)d_in[24]; p.b_out    = (const float*)d_in[25];
    p.W_sfcout = (const float*)d_in[26]; p.b_sfcout = (const float*)d_in[27];
    p.W_mu     = (const float*)d_in[28]; p.b_mu     = (const float*)d_in[29];
    p.W_lv     = (const float*)d_in[30]; p.b_lv     = (const float*)d_in[31];
    p.out = (float*)d_out;

    cudaFuncSetAttribute(xpre_simt, cudaFuncAttributeMaxDynamicSharedMemorySize, XP_SMEM);
    cudaFuncSetAttribute(rnn1_seq,  cudaFuncAttributeMaxDynamicSharedMemorySize, SEQ_SMEM);
    cudaFuncSetAttribute(rnn2_seq,  cudaFuncAttributeMaxDynamicSharedMemorySize, SEQ_SMEM);

    xpre_simt<<<148, 512, XP_SMEM>>>(0, 68, p.inputs_main, p.rnn1_mem, p.Wx1, p.Wxs1);
    rnn1_seq<<<NB2, 256, SEQ_SMEM>>>(p);
    xpre_simt<<<148, 512, XP_SMEM>>>(1, 64, p.inputs_main, p.rnn1_mem, p.Wx2, p.Wxs2);
    rnn2_seq<<<NB2, 256, SEQ_SMEM>>>(p);
    latent_kernel<<<dim3(BATCH / LTB, LEV / LPB), 256>>>(p.W_lat, p.b_lat, p.W_out, p.b_out, p.out);
}

// round 15
// speedup vs baseline: 2.3872x; 1.0500x over previous
#include <cuda_runtime.h>
#include <math.h>
#include <stdint.h>

#define LEV 60
#define BATCH 4096
#define NXI 4
#define NH 64
#define NMEM 64
#define NSFC 17
#define NYO 4
#define NG 256
#define NWCOL 320
#define XC 320
#define KD2 68              // padded K stride
#define TB2 16              // rows per seq CTA (2 CTAs/SM)
#define NB2 (BATCH / TB2)   // 256
#define LTB 32
#define LPB 5

#define OFF_SFC (BATCH * LEV * NYO)
#define OFF_MEM (OFF_SFC + BATCH * 3)

__device__ float g_scratch[(size_t)LEV * BATCH * NH];
__device__ float g_X1[(size_t)LEV * BATCH * XC];
__device__ float g_X2[(size_t)LEV * BATCH * XC];

struct Params {
    const float *inputs_main, *inputs_aux, *rnn1_mem, *eps1, *eps2, *eps_sfc;
    const float *W_sfc, *b_sfc, *W_sfc2, *b_sfc2, *W_toa, *b_toa, *W_toa2, *b_toa2;
    const float *Wx1, *Wh1, *Wxs1, *Whs1, *Wx2, *Wh2, *Wxs2, *Whs2;
    const float *W_lat, *b_lat, *W_out, *b_out, *W_sfcout, *b_sfcout;
    const float *W_mu, *b_mu, *W_lv, *b_lv;
    float *out;
};

__device__ __forceinline__ float sigmoidf_(float x) {
    return __fdividef(1.0f, 1.0f + __expf(-x));
}
__device__ __forceinline__ float tanhf_(float x) {
    float ax = fabsf(x);
    float e  = __expf(2.0f * ax);
    float t  = 1.0f - __fdividef(2.0f, e + 1.0f);
    return copysignf(t, x);
}
__device__ __forceinline__ unsigned long long fma2_(unsigned long long a,
                                                    unsigned long long b,
                                                    unsigned long long c) {
    unsigned long long d;
    asm("fma.rn.f32x2 %0, %1, %2, %3;" : "=l"(d) : "l"(a), "l"(b), "l"(c));
    return d;
}
__device__ __forceinline__ float pairsum_(unsigned long long v) {
    float lo = __int_as_float((int)(v & 0xffffffffull));
    float hi = __int_as_float((int)(v >> 32));
    return lo + hi;
}

extern __shared__ float smem[];

// =====================================================================
// xpre_simt: X = A @ [Wa|Wb] (FFMA2), persistent, A double-buffered.
// Prefetch: fixed-trip unrolled (registers), division-free.
// mode 0: A = [inputs_main|rnn1_mem] at level 59-s (K=68) -> g_X1
// mode 1: A = g_scratch[s]            (K=64)              -> g_X2
// grid 148 x 512 thr; M=64-row tiles, 3840 total.
// =====================================================================
#define XP_A (64 * KD2)
#define XP_SMEM ((NWCOL * KD2 + 2 * XP_A) * 4)

__device__ __forceinline__ void xpre_fetch_(int mode, int t,
                                            const float* __restrict__ im,
                                            const float* __restrict__ mem,
                                            float pref[9], int fr, int fq) {
    int s = t >> 6, b0t = (t & 63) * 64;
    if (mode == 0) {
        size_t rowbase = ((size_t)(b0t + fr) * LEV + (LEV - 1 - s));
        const float* irow = im + rowbase * NXI;
        const float* mrow = mem + rowbase * NMEM - NXI;
#pragma unroll
        for (int j = 0; j < 9; j++) {
            int k = fq + j * 8;
            float v = 0.f;
            if (k < KD2) v = (k < NXI) ? irow[k] : mrow[k];
            pref[j] = v;
        }
    } else {
        const float* srow = g_scratch + ((size_t)s * BATCH + b0t + fr) * NH;
#pragma unroll
        for (int j = 0; j < 9; j++) {
            int k = fq + j * 8;
            pref[j] = (k < NH) ? srow[k] : 0.f;
        }
    }
}

__device__ __forceinline__ void xpre_commit_(float* __restrict__ dst,
                                             const float pref[9], int fr, int fq) {
    float* d = dst + fr * KD2;
#pragma unroll
    for (int j = 0; j < 9; j++) {
        int k = fq + j * 8;
        if (k < KD2) d[k] = pref[j];
    }
}

__global__ __launch_bounds__(512, 1)
void xpre_simt(int mode, int K, const float* __restrict__ im,
               const float* __restrict__ mem,
               const float* __restrict__ Wa, const float* __restrict__ Wb) {
    float* W_s = smem;                     // [320][KD2]
    float* A_b = smem + NWCOL * KD2;       // [2][64][KD2]
    const int tid = threadIdx.x;
    const int tx = tid & 63;
    const int ty = tid >> 6;               // 0..7, 8 rows each
    const int fr = tid >> 3;               // fetch row 0..63
    const int fq = tid & 7;                // fetch k-octet
    float* Xout = mode ? g_X2 : g_X1;

    for (int idx = tid; idx < NWCOL * KD2; idx += 512) {
        int k = idx / NWCOL, j = idx % NWCOL;
        float v = 0.f;
        if (k < K) v = (j < NG) ? Wa[(size_t)k * NG + j] : Wb[(size_t)k * NH + (j - NG)];
        W_s[j * KD2 + k] = v;
    }

    const int t0 = blockIdx.x;
    float pref[9];
    xpre_fetch_(mode, t0, im, mem, pref, fr, fq);
    xpre_commit_(A_b, pref, fr, fq);
    __syncthreads();

    const float* wbase = W_s + tx * KD2;
    int buf = 0;
    for (int t = t0; t < 3840; t += 148) {
        int tn = t + 148;
        if (tn < 3840) xpre_fetch_(mode, tn, im, mem, pref, fr, fq);

        const float* arow = A_b + buf * XP_A + (ty * 8) * KD2;
        unsigned long long acc[8][5];
#pragma unroll
        for (int u = 0; u < 8; u++)
#pragma unroll
            for (int c = 0; c < 5; c++) acc[u][c] = 0ull;

#pragma unroll 1
        for (int kq = 0; kq < KD2 / 4; kq++) {
            ulonglong2 wv[5];
#pragma unroll
            for (int c = 0; c < 5; c++)
                wv[c] = *(const ulonglong2*)&wbase[c * (64 * KD2) + kq * 4];
#pragma unroll
            for (int u = 0; u < 8; u++) {
                ulonglong2 xv = *(const ulonglong2*)&arow[u * KD2 + kq * 4];
#pragma unroll
                for (int c = 0; c < 5; c++) {
                    acc[u][c] = fma2_(xv.x, wv[c].x, acc[u][c]);
                    acc[u][c] = fma2_(xv.y, wv[c].y, acc[u][c]);
                }
            }
        }
        {
            int s = t >> 6, b0t = (t & 63) * 64;
            float* op = Xout + ((size_t)s * BATCH + b0t + ty * 8) * XC + tx;
#pragma unroll
            for (int u = 0; u < 8; u++)
#pragma unroll
                for (int c = 0; c < 5; c++)
                    op[u * XC + c * 64] = pairsum_(acc[u][c]);
        }
        if (tn < 3840)
            xpre_commit_(A_b + (buf ^ 1) * XP_A, pref, fr, fq);
        __syncthreads();
        buf ^= 1;
    }
}

// =====================================================================
// Sequential h-only recurrence, K=64, TB2=16, 2 CTAs/SM.
// Register pointwise, double-buffered xh, 1 sync/step, immediate-offset
// global addressing via per-thread base pointers.
// =====================================================================
#define XH1 (TB2 * KD2)
#define SEQ_SMEM ((NWCOL * KD2 + 2 * XH1) * 4)

__device__ __forceinline__ void stage_Wh_(float* __restrict__ W_s,
                                          const float* __restrict__ Wh,
                                          const float* __restrict__ Whs, int tid) {
    for (int idx = tid; idx < NWCOL * KD2; idx += 256) {
        int k = idx / NWCOL, j = idx % NWCOL;
        float v = 0.f;
        if (k < NH) v = (j < NG) ? Wh[(size_t)k * NG + j] : Whs[(size_t)k * NH + (j - NG)];
        W_s[j * KD2 + k] = v;
    }
}

// One LSTM step. xp/ep/sp are per-thread pointers (already + tx, row ty*4).
__device__ __forceinline__ void seq_step_(const float* __restrict__ wbase,
                                          const float* __restrict__ cur,
                                          float* __restrict__ nxt,
                                          float* __restrict__ c_reg,
                                          int tx, int ty,
                                          const float* __restrict__ xp,
                                          const float* __restrict__ ep,
                                          float* __restrict__ sp) {
    // prefetch X and eps with immediate offsets (latency hidden under GEMM)
    float Xr[20], ge[4];
#pragma unroll
    for (int u = 0; u < 4; u++) {
#pragma unroll
        for (int c = 0; c < 5; c++)
            Xr[u * 5 + c] = xp[u * XC + c * 64];
        ge[u] = ep[u * NH];
    }

    const float* arow = cur + (ty * 4) * KD2;
    unsigned long long acc[4][5];
#pragma unroll
    for (int u = 0; u < 4; u++)
#pragma unroll
        for (int c = 0; c < 5; c++) acc[u][c] = 0ull;
#pragma unroll 1
    for (int kq = 0; kq < 16; kq++) {
        ulonglong2 wv[5];
#pragma unroll
        for (int c = 0; c < 5; c++)
            wv[c] = *(const ulonglong2*)&wbase[c * (64 * KD2) + kq * 4];
#pragma unroll
        for (int u = 0; u < 4; u++) {
            ulonglong2 xv = *(const ulonglong2*)&arow[u * KD2 + kq * 4];
#pragma unroll
            for (int c = 0; c < 5; c++) {
                acc[u][c] = fma2_(xv.x, wv[c].x, acc[u][c]);
                acc[u][c] = fma2_(xv.y, wv[c].y, acc[u][c]);
            }
        }
    }
    float* nrow = nxt + (ty * 4) * KD2 + tx;
#pragma unroll
    for (int u = 0; u < 4; u++) {
        float iv = sigmoidf_(pairsum_(acc[u][0]) + Xr[u * 5 + 0]);
        float fv = sigmoidf_(pairsum_(acc[u][1]) + Xr[u * 5 + 1]);
        float gt = tanhf_(pairsum_(acc[u][2]) + Xr[u * 5 + 2]);
        float ov = sigmoidf_(pairsum_(acc[u][3]) + Xr[u * 5 + 3]);
        float lv = pairsum_(acc[u][4]) + Xr[u * 5 + 4];
        float cc = fv * c_reg[u] + iv * gt;
        c_reg[u] = cc;
        float h  = ov * tanhf_(cc) + ge[u] * __expf(0.5f * lv);
        nrow[u * KD2] = h;
        sp[u * NH] = h;
    }
}

__global__ __launch_bounds__(256, 2)
void rnn1_seq(Params p) {
    const int tid = threadIdx.x;
    const int b0  = blockIdx.x * TB2;
    float* W_s = smem;
    float* xh  = smem + NWCOL * KD2;   // [2][16][KD2]
    const int tx = tid & 63, ty = tid >> 6;
    float c_reg[4];

    stage_Wh_(W_s, p.Wh1, p.Whs1, tid);
#pragma unroll
    for (int u = 0; u < 4; u++) {
        int row = ty * 4 + u;
        const float* auxrow = p.inputs_aux + (size_t)(b0 + row) * NSFC;
        float ah = p.b_sfc[tx], ac = p.b_sfc2[tx];
        for (int k = 0; k < NSFC; k++) {
            float a = auxrow[k];
            ah = fmaf(a, p.W_sfc[k * NH + tx], ah);
            ac = fmaf(a, p.W_sfc2[k * NH + tx], ac);
        }
        xh[row * KD2 + tx] = tanhf_(ah);
        c_reg[u] = tanhf_(ac);
    }
    __syncthreads();

    const float* wbase = W_s + tx * KD2;
    const float* xp = g_X1 + (size_t)(b0 + ty * 4) * XC + tx;
    const float* ep = p.eps1 + (size_t)(b0 + ty * 4) * NH + tx;
    float* sp = g_scratch + ((size_t)(LEV - 1) * BATCH + b0 + ty * 4) * NH + tx;

    for (int s = 0; s < LEV; s++) {
        const float* cur = xh + (s & 1) * XH1;
        float* nxt = xh + ((s + 1) & 1) * XH1;
        seq_step_(wbase, cur, nxt, c_reg, tx, ty, xp, ep, sp);
        xp += (size_t)BATCH * XC;
        ep += (size_t)BATCH * NH;
        sp -= (size_t)BATCH * NH;
        __syncthreads();
    }
}

__global__ __launch_bounds__(256, 2)
void rnn2_seq(Params p) {
    const int tid = threadIdx.x;
    const int b0  = blockIdx.x * TB2;
    float* W_s = smem;
    float* xh  = smem + NWCOL * KD2;
    const int tx = tid & 63, ty = tid >> 6;
    float c_reg[4];

    stage_Wh_(W_s, p.Wh2, p.Whs2, tid);
#pragma unroll
    for (int u = 0; u < 4; u++) {
        int row = ty * 4 + u;
        float x0 = p.inputs_aux[(size_t)(b0 + row) * NSFC + 1];
        float x1 = p.inputs_aux[(size_t)(b0 + row) * NSFC + 6];
        float ah = fmaf(x0, p.W_toa[tx],  fmaf(x1, p.W_toa[NH + tx],  p.b_toa[tx]));
        float ac = fmaf(x0, p.W_toa2[tx], fmaf(x1, p.W_toa2[NH + tx], p.b_toa2[tx]));
        xh[row * KD2 + tx] = tanhf_(ah);
        c_reg[u] = tanhf_(ac);
    }
    __syncthreads();

    const float* wbase = W_s + tx * KD2;
    const float* xp = g_X2 + (size_t)(b0 + ty * 4) * XC + tx;
    const float* ep = p.eps2 + (size_t)(b0 + ty * 4) * NH + tx;
    float* sp = g_scratch + (size_t)(b0 + ty * 4) * NH + tx;

    for (int s = 0; s < LEV; s++) {
        const float* cur = xh + (s & 1) * XH1;
        float* nxt = xh + ((s + 1) & 1) * XH1;
        seq_step_(wbase, cur, nxt, c_reg, tx, ty, xp, ep, sp);
        xp += (size_t)BATCH * XC;
        ep += (size_t)BATCH * NH;
        sp += (size_t)BATCH * NH;
        __syncthreads();
    }

    // surface heads from last hidden: step 59 wrote xh buffer 0
    if (tid < TB2) {
        const float* hl = xh;
        int r = tid;
        size_t b = b0 + r;
        float rad = p.b_sfcout[0];
        float mu0 = p.b_mu[0], mu1 = p.b_mu[1];
        float lv0 = p.b_lv[0], lv1 = p.b_lv[1];
        for (int k = 0; k < NH; k++) {
            float h = hl[r * KD2 + k];
            rad = fmaf(h, p.W_sfcout[k], rad);
            mu0 = fmaf(h, p.W_mu[k * 2 + 0], mu0);
            mu1 = fmaf(h, p.W_mu[k * 2 + 1], mu1);
            lv0 = fmaf(h, p.W_lv[k * 2 + 0], lv0);
            lv1 = fmaf(h, p.W_lv[k * 2 + 1], lv1);
        }
        float e0 = p.eps_sfc[b * 2 + 0], e1 = p.eps_sfc[b * 2 + 1];
        p.out[OFF_SFC + b * 3 + 0] = mu0 + e0 * __expf(0.5f * lv0);
        p.out[OFF_SFC + b * 3 + 1] = mu1 + e1 * __expf(0.5f * lv1);
        p.out[OFF_SFC + b * 3 + 2] = rad;
    }
}

// ===== latent + out heads; LPB levels per block, occ 4, fma2 =====
__global__ __launch_bounds__(256, 4)
void latent_kernel(const float* __restrict__ W_lat, const float* __restrict__ b_lat,
                   const float* __restrict__ W_out, const float* __restrict__ b_out,
                   float* __restrict__ out) {
    __shared__ float Wl[NH * KD2];
    __shared__ float wout[NH * NYO + NYO];
    __shared__ float xt[LTB * KD2];
    __shared__ float lat[LTB * KD2];

    const int l0 = blockIdx.y * LPB;
    const int b0 = blockIdx.x * LTB;
    const int tid = threadIdx.x;
    const int tx = tid & 63;
    const int ty = tid >> 6;

    for (int i = tid; i < NH * NH; i += 256) {
        int k = i >> 6, m = i & 63;
        Wl[m * KD2 + k] = W_lat[i];
    }
    for (int i = tid; i < NH * NYO; i += 256) wout[i] = W_out[i];
    if (tid < NYO) wout[NH * NYO + tid] = b_out[tid];
    float bl = b_lat[tx];

    for (int li = 0; li < LPB; li++) {
        int l = l0 + li;
        __syncthreads();
        const float* src = g_scratch + ((size_t)l * BATCH + b0) * NH;
        for (int i = tid; i < LTB * NH / 4; i += 256) {
            int r = i >> 4, q = i & 15;
            *(float4*)&xt[r * KD2 + q * 4] = *(const float4*)&src[r * NH + q * 4];
        }
        __syncthreads();

        unsigned long long accL[8];
#pragma unroll
        for (int u = 0; u < 8; u++) accL[u] = 0ull;
#pragma unroll 1
        for (int kq = 0; kq < 16; kq++) {
            ulonglong2 wv = *(const ulonglong2*)&Wl[tx * KD2 + kq * 4];
#pragma unroll
            for (int u = 0; u < 8; u++) {
                ulonglong2 xv = *(const ulonglong2*)&xt[(ty * 8 + u) * KD2 + kq * 4];
                accL[u] = fma2_(xv.x, wv.x, accL[u]);
                accL[u] = fma2_(xv.y, wv.y, accL[u]);
            }
        }
#pragma unroll
        for (int u = 0; u < 8; u++) {
            int r = ty * 8 + u;
            size_t b = b0 + r;
            float v = pairsum_(accL[u]) + bl;
            lat[r * KD2 + tx] = v;
            out[OFF_MEM + (b * LEV + l) * NMEM + tx] = v;
        }
        __syncthreads();

        if (tid < LTB * NYO) {
            int r = tid >> 2, y = tid & 3;
            float a = wout[NH * NYO + y];
            for (int m = 0; m < NH; m += 4) {
                a = fmaf(lat[r * KD2 + m + 0], wout[(m + 0) * NYO + y], a);
                a = fmaf(lat[r * KD2 + m + 1], wout[(m + 1) * NYO + y], a);
                a = fmaf(lat[r * KD2 + m + 2], wout[(m + 2) * NYO + y], a);
                a = fmaf(lat[r * KD2 + m + 3], wout[(m + 3) * NYO + y], a);
            }
            out[(size_t)(b0 + r) * (LEV * NYO) + l * NYO + y] = a;
        }
    }
}

extern "C" void kernel_launch(void* const* d_in, const int* in_sizes, int n_in,
                              void* d_out, int out_size) {
    Params p;
    p.inputs_main = (const float*)d_in[0];
    p.inputs_aux  = (const float*)d_in[1];
    p.rnn1_mem    = (const float*)d_in[2];
    p.eps1        = (const float*)d_in[3];
    p.eps2        = (const float*)d_in[4];
    p.eps_sfc     = (const float*)d_in[5];
    p.W_sfc   = (const float*)d_in[6];  p.b_sfc   = (const float*)d_in[7];
    p.W_sfc2  = (const float*)d_in[8];  p.b_sfc2  = (const float*)d_in[9];
    p.W_toa   = (const float*)d_in[10]; p.b_toa   = (const float*)d_in[11];
    p.W_toa2  = (const float*)d_in[12]; p.b_toa2  = (const float*)d_in[13];
    p.Wx1  = (const float*)d_in[14]; p.Wh1  = (const float*)d_in[15];
    p.Wxs1 = (const float*)d_in[16]; p.Whs1 = (const float*)d_in[17];
    p.Wx2  = (const float*)d_in[18]; p.Wh2  = (const float*)d_in[19];
    p.Wxs2 = (const float*)d_in[20]; p.Whs2 = (const float*)d_in[21];
    p.W_lat    = (const float*)d_in[22]; p.b_lat    = (const float*)d_in[23];
    p.W_out    = (const float*)d_in[24]; p.b_out    = (const float*)d_in[25];
    p.W_sfcout = (const float*)d_in[26]; p.b_sfcout = (const float*)d_in[27];
    p.W_mu     = (const float*)d_in[28]; p.b_mu     = (const float*)d_in[29];
    p.W_lv     = (const float*)d_in[30]; p.b_lv     = (const float*)d_in[31];
    p.out = (float*)d_out;

    cudaFuncSetAttribute(xpre_simt, cudaFuncAttributeMaxDynamicSharedMemorySize, XP_SMEM);
    cudaFuncSetAttribute(rnn1_seq,  cudaFuncAttributeMaxDynamicSharedMemorySize, SEQ_SMEM);
    cudaFuncSetAttribute(rnn2_seq,  cudaFuncAttributeMaxDynamicSharedMemorySize, SEQ_SMEM);

    xpre_simt<<<148, 512, XP_SMEM>>>(0, 68, p.inputs_main, p.rnn1_mem, p.Wx1, p.Wxs1);
    rnn1_seq<<<NB2, 256, SEQ_SMEM>>>(p);
    xpre_simt<<<148, 512, XP_SMEM>>>(1, 64, p.inputs_main, p.rnn1_mem, p.Wx2, p.Wxs2);
    rnn2_seq<<<NB2, 256, SEQ_SMEM>>>(p);
    latent_kernel<<<dim3(BATCH / LTB, LEV / LPB), 256>>>(p.W_lat, p.b_lat, p.W_out, p.b_out, p.out);
}